// round 5
// baseline (speedup 1.0000x reference)
#include <cuda_runtime.h>
#include <float.h>

#define NQ    16384
#define HID   128
#define PROP  64
#define SPACE 4
#define KNN   40
#define TJ    512            // candidate tile in smem (knn)
#define WPB   16             // warps (=queries) per knn block

// ---------------- scratch (device globals; no allocation allowed) ----------------
__device__ float g_t1[NQ * HID];
__device__ float g_t2[NQ * HID];
__device__ float g_xcat[NQ * 256];     // [x (128) | agg_mean (64) | agg_max (64)]
__device__ float g_xg[NQ * HID];
__device__ float g_s[NQ * SPACE];
__device__ float g_s2[NQ];
__device__ float g_h[NQ * PROP];
__device__ float g_kd[NQ * KNN];
__device__ int   g_kj[NQ * KNN];

// ---------------- generic fp32 GEMM, double-buffered ------------------------------
// C = act(A[M,Kd] @ W[Kd,Nd] + b). BM=64, BN=128, BK=16, 256 thr, tile 8x4.
__global__ __launch_bounds__(256) void gemm_kernel(
    const float* __restrict__ A, int lda,
    const float* __restrict__ W,          // row-major [Kd, Nd]
    const float* __restrict__ bias,
    float* __restrict__ C, int ldc,
    int Kd, int Nd, int relu)
{
    __shared__ float As[2][64][16];
    __shared__ float Bs[2][16][128];

    const int tid = threadIdx.x;
    const int m0  = blockIdx.x * 64;
    const int tn  = tid & 31;
    const int tm  = tid >> 5;
    const int arow = tid >> 2;
    const int ak   = (tid & 3) * 4;
    const int bn   = (tid & 31) * 4;
    const int bk   = tid >> 5;

    float acc[8][4];
#pragma unroll
    for (int i = 0; i < 8; i++)
#pragma unroll
        for (int j = 0; j < 4; j++) acc[i][j] = 0.f;

    float4 av, bv0, bv1;

#define GEMM_LDG(K0)                                                      \
    {                                                                     \
        const float* ap = A + (long)(m0 + arow) * lda + (K0) + ak;        \
        av.x = ((K0) + ak + 0 < Kd) ? ap[0] : 0.f;                        \
        av.y = ((K0) + ak + 1 < Kd) ? ap[1] : 0.f;                        \
        av.z = ((K0) + ak + 2 < Kd) ? ap[2] : 0.f;                        \
        av.w = ((K0) + ak + 3 < Kd) ? ap[3] : 0.f;                        \
        bv0 = make_float4(0.f, 0.f, 0.f, 0.f);                            \
        bv1 = make_float4(0.f, 0.f, 0.f, 0.f);                            \
        if ((K0) + bk < Kd) {                                             \
            const float* wp = W + (long)((K0) + bk) * Nd + bn;            \
            if (bn + 0 < Nd) bv0.x = wp[0];                               \
            if (bn + 1 < Nd) bv0.y = wp[1];                               \
            if (bn + 2 < Nd) bv0.z = wp[2];                               \
            if (bn + 3 < Nd) bv0.w = wp[3];                               \
        }                                                                 \
        if ((K0) + bk + 8 < Kd) {                                         \
            const float* wp = W + (long)((K0) + bk + 8) * Nd + bn;        \
            if (bn + 0 < Nd) bv1.x = wp[0];                               \
            if (bn + 1 < Nd) bv1.y = wp[1];                               \
            if (bn + 2 < Nd) bv1.z = wp[2];                               \
            if (bn + 3 < Nd) bv1.w = wp[3];                               \
        }                                                                 \
    }

#define GEMM_STS(BUF)                                                     \
    {                                                                     \
        *(float4*)&As[BUF][arow][ak]   = av;                              \
        *(float4*)&Bs[BUF][bk][bn]     = bv0;                             \
        *(float4*)&Bs[BUF][bk + 8][bn] = bv1;                             \
    }

    const int nT = (Kd + 15) / 16;
    GEMM_LDG(0);
    GEMM_STS(0);
    __syncthreads();

    for (int t = 0; t < nT; t++) {
        const int cur = t & 1;
        if (t + 1 < nT) GEMM_LDG((t + 1) * 16);

#pragma unroll
        for (int kk4 = 0; kk4 < 16; kk4 += 4) {
            float4 b0 = *(const float4*)&Bs[cur][kk4 + 0][tn * 4];
            float4 b1 = *(const float4*)&Bs[cur][kk4 + 1][tn * 4];
            float4 b2 = *(const float4*)&Bs[cur][kk4 + 2][tn * 4];
            float4 b3 = *(const float4*)&Bs[cur][kk4 + 3][tn * 4];
#pragma unroll
            for (int i = 0; i < 8; i++) {
                float4 a = *(const float4*)&As[cur][tm * 8 + i][kk4];
                acc[i][0] = fmaf(a.x, b0.x, acc[i][0]);
                acc[i][1] = fmaf(a.x, b0.y, acc[i][1]);
                acc[i][2] = fmaf(a.x, b0.z, acc[i][2]);
                acc[i][3] = fmaf(a.x, b0.w, acc[i][3]);
                acc[i][0] = fmaf(a.y, b1.x, acc[i][0]);
                acc[i][1] = fmaf(a.y, b1.y, acc[i][1]);
                acc[i][2] = fmaf(a.y, b1.z, acc[i][2]);
                acc[i][3] = fmaf(a.y, b1.w, acc[i][3]);
                acc[i][0] = fmaf(a.z, b2.x, acc[i][0]);
                acc[i][1] = fmaf(a.z, b2.y, acc[i][1]);
                acc[i][2] = fmaf(a.z, b2.z, acc[i][2]);
                acc[i][3] = fmaf(a.z, b2.w, acc[i][3]);
                acc[i][0] = fmaf(a.w, b3.x, acc[i][0]);
                acc[i][1] = fmaf(a.w, b3.y, acc[i][1]);
                acc[i][2] = fmaf(a.w, b3.z, acc[i][2]);
                acc[i][3] = fmaf(a.w, b3.w, acc[i][3]);
            }
        }

        if (t + 1 < nT) GEMM_STS(cur ^ 1);
        __syncthreads();
    }

#pragma unroll
    for (int i = 0; i < 8; i++) {
        int row = m0 + tm * 8 + i;
#pragma unroll
        for (int j = 0; j < 4; j++) {
            int col = tn * 4 + j;
            if (col < Nd) {
                float v = acc[i][j] + bias[col];
                if (relu) v = fmaxf(v, 0.f);
                C[(long)row * ldc + col] = v;
            }
        }
    }
}

// ---------------- fused lin_s + s2: s = xcat[:, :128] @ Wg + bg; s2 = |s|^2 ------
__global__ __launch_bounds__(256) void gs_kernel(
    const float* __restrict__ xcat,
    const float* __restrict__ Wg,     // [128, 4]
    const float* __restrict__ bg,
    float4* __restrict__ s, float* __restrict__ s2)
{
    __shared__ float4 Ws[128];
    const int tid = threadIdx.x;
    if (tid < 128) Ws[tid] = ((const float4*)Wg)[tid];
    __syncthreads();

    const int row = blockIdx.x * 256 + tid;
    const float4* xr = (const float4*)(xcat + (long)row * 256);
    float4 acc = make_float4(bg[0], bg[1], bg[2], bg[3]);
#pragma unroll
    for (int k4 = 0; k4 < 32; k4++) {
        float4 xv = xr[k4];
        float4 w0 = Ws[k4 * 4 + 0];
        float4 w1 = Ws[k4 * 4 + 1];
        float4 w2 = Ws[k4 * 4 + 2];
        float4 w3 = Ws[k4 * 4 + 3];
        acc.x = fmaf(xv.x, w0.x, acc.x); acc.y = fmaf(xv.x, w0.y, acc.y);
        acc.z = fmaf(xv.x, w0.z, acc.z); acc.w = fmaf(xv.x, w0.w, acc.w);
        acc.x = fmaf(xv.y, w1.x, acc.x); acc.y = fmaf(xv.y, w1.y, acc.y);
        acc.z = fmaf(xv.y, w1.z, acc.z); acc.w = fmaf(xv.y, w1.w, acc.w);
        acc.x = fmaf(xv.z, w2.x, acc.x); acc.y = fmaf(xv.z, w2.y, acc.y);
        acc.z = fmaf(xv.z, w2.z, acc.z); acc.w = fmaf(xv.z, w2.w, acc.w);
        acc.x = fmaf(xv.w, w3.x, acc.x); acc.y = fmaf(xv.w, w3.y, acc.y);
        acc.z = fmaf(xv.w, w3.z, acc.z); acc.w = fmaf(xv.w, w3.w, acc.w);
    }
    s[row] = acc;
    s2[row] = acc.x * acc.x + acc.y * acc.y + acc.z * acc.z + acc.w * acc.w;
}

// ---------------- kNN helpers: flush pending-32 into sorted-64 list --------------
__device__ __forceinline__ void warp_flush(
    float& L0v, int& L0j, float& L1v, int& L1j,
    float& Pv, int& Pj, int& cnt, float& thrE, int lane)
{
    const unsigned F = 0xffffffffu;
    if (lane >= cnt) { Pv = FLT_MAX; Pj = 0x7FFFFFFF; }

    // bitonic sort-32 ascending on (Pv, Pj)
#pragma unroll
    for (int k = 2; k <= 32; k <<= 1) {
#pragma unroll
        for (int j = k >> 1; j > 0; j >>= 1) {
            float ov = __shfl_xor_sync(F, Pv, j);
            int   oj = __shfl_xor_sync(F, Pj, j);
            bool keepMin = ((lane & j) == 0) == ((lane & k) == 0);
            bool take = keepMin ? (ov < Pv) : (ov > Pv);
            if (take) { Pv = ov; Pj = oj; }
        }
    }

    // incorporate reversed pending into row1 (half-cleaner vs padded desc B)
    {
        float rv = __shfl_xor_sync(F, Pv, 31);
        int   rj = __shfl_xor_sync(F, Pj, 31);
        if (rv < L1v) { L1v = rv; L1j = rj; }
    }
    // L (64) is now bitonic; bitonic-merge to ascending.
    // d = 32: between rows, lane-local
    if (L1v < L0v) {
        float tv = L0v; L0v = L1v; L1v = tv;
        int   tj = L0j; L0j = L1j; L1j = tj;
    }
    // d = 16..1 within rows
#pragma unroll
    for (int d = 16; d > 0; d >>= 1) {
        bool low = (lane & d) == 0;
        float o0v = __shfl_xor_sync(F, L0v, d);
        int   o0j = __shfl_xor_sync(F, L0j, d);
        bool t0 = low ? (o0v < L0v) : (o0v > L0v);
        if (t0) { L0v = o0v; L0j = o0j; }
        float o1v = __shfl_xor_sync(F, L1v, d);
        int   o1j = __shfl_xor_sync(F, L1j, d);
        bool t1 = low ? (o1v < L1v) : (o1v > L1v);
        if (t1) { L1v = o1v; L1j = o1j; }
    }
    thrE = __shfl_sync(F, L1v, 7);   // rank 39
    cnt = 0;
}

// ---------------- kNN: warp per query, batched accept + bitonic flush ------------
// e-space values: e = d2 - s2i (monotone in d2).
__global__ __launch_bounds__(WPB * 32) void knn_kernel(
    const float4* __restrict__ s, const float* __restrict__ s2,
    float* __restrict__ kd, int* __restrict__ kj)
{
    __shared__ float4 sj[TJ];
    __shared__ float  s2j[TJ];

    const unsigned F = 0xffffffffu;
    const int lane = threadIdx.x & 31;
    const int warp = threadIdx.x >> 5;
    const int q    = blockIdx.x * WPB + warp;

    const float4 si = s[q];
    const float s2i = s2[q];
    const float m2x = -2.f * si.x, m2y = -2.f * si.y;
    const float m2z = -2.f * si.z, m2w = -2.f * si.w;

    float L0v = FLT_MAX, L1v = FLT_MAX;
    int   L0j = 0x7FFFFFFF, L1j = 0x7FFFFFFF;
    float Pv = FLT_MAX; int Pj = 0x7FFFFFFF;
    int   cnt = 0;
    float thrE = FLT_MAX;

    for (int t0 = 0; t0 < NQ; t0 += TJ) {
        __syncthreads();
        sj[threadIdx.x]  = s[t0 + threadIdx.x];
        s2j[threadIdx.x] = s2[t0 + threadIdx.x];
        __syncthreads();

        for (int it = 0; it < TJ / 32; it++) {
            const int ci = it * 32 + lane;
            float4 c = sj[ci];
            float e = fmaf(m2x, c.x,
                      fmaf(m2y, c.y,
                      fmaf(m2z, c.z,
                      fmaf(m2w, c.w, s2j[ci]))));
            unsigned m = __ballot_sync(F, e < thrE);
            if (m) {
                int h = __popc(m);
                if (cnt + h > 32) {
                    warp_flush(L0v, L0j, L1v, L1j, Pv, Pj, cnt, thrE, lane);
                    m = __ballot_sync(F, e < thrE);
                    h = __popc(m);
                }
                if (m) {
                    int r = lane - cnt;
                    int off = (r < 0) ? 1 : (r + 1);
                    unsigned src = __fns(m, 0, off);
                    float pv = __shfl_sync(F, e, src & 31);
                    if (r >= 0 && r < h) {
                        Pv = pv;
                        Pj = t0 + it * 32 + (int)(src & 31);
                    }
                    cnt += h;
                }
            }
        }
    }
    if (cnt > 0) warp_flush(L0v, L0j, L1v, L1j, Pv, Pj, cnt, thrE, lane);

    // ranks 0..39 (set-exact; order irrelevant downstream)
    kd[q * KNN + lane] = L0v + s2i;
    kj[q * KNN + lane] = L0j;
    if (lane < KNN - 32) {
        kd[q * KNN + 32 + lane] = L1v + s2i;
        kj[q * KNN + 32 + lane] = L1j;
    }
}

// ---------------- aggregate: warp per query, mean||max of h[idx]*w ---------------
__global__ void aggregate_kernel(
    const float* __restrict__ h, const float* __restrict__ kd,
    const int* __restrict__ kj, float* __restrict__ xcat)
{
    int gw   = (blockIdx.x * blockDim.x + threadIdx.x) >> 5;  // query
    int lane = threadIdx.x & 31;

    const float* dd = kd + gw * KNN;
    const int*   jj = kj + gw * KNN;

    float m0 = 0.f, m1 = 0.f;
    float x0 = -FLT_MAX, x1 = -FLT_MAX;
#pragma unroll
    for (int k = 0; k < KNN; k++) {
        int   j = jj[k];
        float w = expf(-10.f * fmaxf(dd[k], 0.f));
        float v0 = h[j * PROP + lane] * w;
        float v1 = h[j * PROP + 32 + lane] * w;
        m0 += v0; m1 += v1;
        x0 = fmaxf(x0, v0); x1 = fmaxf(x1, v1);
    }
    float* out = xcat + (long)gw * 256 + 128;
    const float inv = 1.f / (float)KNN;
    out[lane]      = m0 * inv;
    out[32 + lane] = m1 * inv;
    out[64 + lane] = x0;
    out[96 + lane] = x1;
}

// =================================================================================
extern "C" void kernel_launch(void* const* d_in, const int* in_sizes, int n_in,
                              void* d_out, int out_size)
{
    const float* x    = (const float*)d_in[0];
    const float* fc1W = (const float*)d_in[1];
    const float* fc1b = (const float*)d_in[2];
    const float* fc2W = (const float*)d_in[3];
    const float* fc2b = (const float*)d_in[4];
    const float* gsW  = (const float*)d_in[5];
    const float* gsb  = (const float*)d_in[6];
    const float* ghW  = (const float*)d_in[7];
    const float* ghb  = (const float*)d_in[8];
    const float* goW  = (const float*)d_in[9];
    const float* gob  = (const float*)d_in[10];
    const float* d1W  = (const float*)d_in[11];
    const float* d1b  = (const float*)d_in[12];
    const float* d2W  = (const float*)d_in[13];
    const float* d2b  = (const float*)d_in[14];
    const float* d3W  = (const float*)d_in[15];
    const float* d3b  = (const float*)d_in[16];
    const float* fc3W = (const float*)d_in[17];
    const float* fc3b = (const float*)d_in[18];
    const float* fc4W = (const float*)d_in[19];
    const float* fc4b = (const float*)d_in[20];
    float* out = (float*)d_out;

    float *t1, *t2, *xcat, *xg, *s, *s2n, *h, *kd;
    int *kj;
    cudaGetSymbolAddress((void**)&t1,   g_t1);
    cudaGetSymbolAddress((void**)&t2,   g_t2);
    cudaGetSymbolAddress((void**)&xcat, g_xcat);
    cudaGetSymbolAddress((void**)&xg,   g_xg);
    cudaGetSymbolAddress((void**)&s,    g_s);
    cudaGetSymbolAddress((void**)&s2n,  g_s2);
    cudaGetSymbolAddress((void**)&h,    g_h);
    cudaGetSymbolAddress((void**)&kd,   g_kd);
    cudaGetSymbolAddress((void**)&kj,   g_kj);

    const int GB = NQ / 64;  // gemm grid

    gemm_kernel<<<GB, 256>>>(x, 9, fc1W, fc1b, t1, HID, 9, HID, 1);
    gemm_kernel<<<GB, 256>>>(t1, HID, fc2W, fc2b, xcat, 256, HID, HID, 1);

    for (int l = 0; l < 4; l++) {
        gs_kernel<<<NQ / 256, 256>>>(xcat, gsW + l * HID * SPACE, gsb + l * SPACE,
                                     (float4*)s, s2n);
        gemm_kernel<<<GB, 256>>>(xcat, 256, ghW + l * HID * PROP, ghb + l * PROP,
                                 h, PROP, HID, PROP, 0);
        knn_kernel<<<NQ / WPB, WPB * 32>>>((const float4*)s, s2n, kd, kj);
        aggregate_kernel<<<NQ / 8, 256>>>(h, kd, kj, xcat);
        gemm_kernel<<<GB, 256>>>(xcat, 256, goW + l * 256 * HID, gob + l * HID,
                                 xg, HID, 256, HID, 0);
        gemm_kernel<<<GB, 256>>>(xg, HID, d1W + l * HID * HID, d1b + l * HID,
                                 t1, HID, HID, HID, 1);
        gemm_kernel<<<GB, 256>>>(t1, HID, d2W + l * HID * HID, d2b + l * HID,
                                 t2, HID, HID, HID, 1);
        gemm_kernel<<<GB, 256>>>(t2, HID, d3W + l * HID * HID, d3b + l * HID,
                                 xcat, 256, HID, HID, 1);
    }

    gemm_kernel<<<GB, 256>>>(xcat, 256, fc3W, fc3b, t1, HID, HID, HID, 1);
    gemm_kernel<<<GB, 256>>>(t1, HID, fc4W, fc4b, out, 4, HID, 4, 0);
}

// round 8
// speedup vs baseline: 1.1744x; 1.1744x over previous
#include <cuda_runtime.h>
#include <float.h>

#define NQ    16384
#define HID   128
#define PROP  64
#define SPACE 4
#define KNN   40
#define TJ    512            // candidate tile in smem (knn)
#define WPB   16             // warps (=queries) per knn block

// ---------------- scratch (device globals; no allocation allowed) ----------------
__device__ float g_t1[NQ * HID];
__device__ float g_t2[NQ * HID];
__device__ float g_xcat[NQ * 256];     // [x (128) | agg_mean (64) | agg_max (64)]
__device__ float g_xg[NQ * HID];
__device__ float g_s[NQ * SPACE];
__device__ float g_s2[NQ];
__device__ float g_h[NQ * PROP];
__device__ float g_kd[NQ * KNN];
__device__ int   g_kj[NQ * KNN];

// ---------------- generic fp32 GEMM, double-buffered ------------------------------
// C = act(A[M,Kd] @ W[Kd,Nd] + b). BM=64, BN=128, BK=16, 256 thr, tile 8x4.
__global__ __launch_bounds__(256) void gemm_kernel(
    const float* __restrict__ A, int lda,
    const float* __restrict__ W,          // row-major [Kd, Nd]
    const float* __restrict__ bias,
    float* __restrict__ C, int ldc,
    int Kd, int Nd, int relu)
{
    __shared__ float As[2][64][16];
    __shared__ float Bs[2][16][128];

    const int tid = threadIdx.x;
    const int m0  = blockIdx.x * 64;
    const int tn  = tid & 31;
    const int tm  = tid >> 5;
    const int arow = tid >> 2;
    const int ak   = (tid & 3) * 4;
    const int bn   = (tid & 31) * 4;
    const int bk   = tid >> 5;

    float acc[8][4];
#pragma unroll
    for (int i = 0; i < 8; i++)
#pragma unroll
        for (int j = 0; j < 4; j++) acc[i][j] = 0.f;

    float4 av, bv0, bv1;

#define GEMM_LDG(K0)                                                      \
    {                                                                     \
        const float* ap = A + (long)(m0 + arow) * lda + (K0) + ak;        \
        av.x = ((K0) + ak + 0 < Kd) ? ap[0] : 0.f;                        \
        av.y = ((K0) + ak + 1 < Kd) ? ap[1] : 0.f;                        \
        av.z = ((K0) + ak + 2 < Kd) ? ap[2] : 0.f;                        \
        av.w = ((K0) + ak + 3 < Kd) ? ap[3] : 0.f;                        \
        bv0 = make_float4(0.f, 0.f, 0.f, 0.f);                            \
        bv1 = make_float4(0.f, 0.f, 0.f, 0.f);                            \
        if ((K0) + bk < Kd) {                                             \
            const float* wp = W + (long)((K0) + bk) * Nd + bn;            \
            if (bn + 0 < Nd) bv0.x = wp[0];                               \
            if (bn + 1 < Nd) bv0.y = wp[1];                               \
            if (bn + 2 < Nd) bv0.z = wp[2];                               \
            if (bn + 3 < Nd) bv0.w = wp[3];                               \
        }                                                                 \
        if ((K0) + bk + 8 < Kd) {                                         \
            const float* wp = W + (long)((K0) + bk + 8) * Nd + bn;        \
            if (bn + 0 < Nd) bv1.x = wp[0];                               \
            if (bn + 1 < Nd) bv1.y = wp[1];                               \
            if (bn + 2 < Nd) bv1.z = wp[2];                               \
            if (bn + 3 < Nd) bv1.w = wp[3];                               \
        }                                                                 \
    }

#define GEMM_STS(BUF)                                                     \
    {                                                                     \
        *(float4*)&As[BUF][arow][ak]   = av;                              \
        *(float4*)&Bs[BUF][bk][bn]     = bv0;                             \
        *(float4*)&Bs[BUF][bk + 8][bn] = bv1;                             \
    }

    const int nT = (Kd + 15) / 16;
    GEMM_LDG(0);
    GEMM_STS(0);
    __syncthreads();

    for (int t = 0; t < nT; t++) {
        const int cur = t & 1;
        if (t + 1 < nT) GEMM_LDG((t + 1) * 16);

#pragma unroll
        for (int kk4 = 0; kk4 < 16; kk4 += 4) {
            float4 b0 = *(const float4*)&Bs[cur][kk4 + 0][tn * 4];
            float4 b1 = *(const float4*)&Bs[cur][kk4 + 1][tn * 4];
            float4 b2 = *(const float4*)&Bs[cur][kk4 + 2][tn * 4];
            float4 b3 = *(const float4*)&Bs[cur][kk4 + 3][tn * 4];
#pragma unroll
            for (int i = 0; i < 8; i++) {
                float4 a = *(const float4*)&As[cur][tm * 8 + i][kk4];
                acc[i][0] = fmaf(a.x, b0.x, acc[i][0]);
                acc[i][1] = fmaf(a.x, b0.y, acc[i][1]);
                acc[i][2] = fmaf(a.x, b0.z, acc[i][2]);
                acc[i][3] = fmaf(a.x, b0.w, acc[i][3]);
                acc[i][0] = fmaf(a.y, b1.x, acc[i][0]);
                acc[i][1] = fmaf(a.y, b1.y, acc[i][1]);
                acc[i][2] = fmaf(a.y, b1.z, acc[i][2]);
                acc[i][3] = fmaf(a.y, b1.w, acc[i][3]);
                acc[i][0] = fmaf(a.z, b2.x, acc[i][0]);
                acc[i][1] = fmaf(a.z, b2.y, acc[i][1]);
                acc[i][2] = fmaf(a.z, b2.z, acc[i][2]);
                acc[i][3] = fmaf(a.z, b2.w, acc[i][3]);
                acc[i][0] = fmaf(a.w, b3.x, acc[i][0]);
                acc[i][1] = fmaf(a.w, b3.y, acc[i][1]);
                acc[i][2] = fmaf(a.w, b3.z, acc[i][2]);
                acc[i][3] = fmaf(a.w, b3.w, acc[i][3]);
            }
        }

        if (t + 1 < nT) GEMM_STS(cur ^ 1);
        __syncthreads();
    }

#pragma unroll
    for (int i = 0; i < 8; i++) {
        int row = m0 + tm * 8 + i;
#pragma unroll
        for (int j = 0; j < 4; j++) {
            int col = tn * 4 + j;
            if (col < Nd) {
                float v = acc[i][j] + bias[col];
                if (relu) v = fmaxf(v, 0.f);
                C[(long)row * ldc + col] = v;
            }
        }
    }
}

// ------- thin GEMM (Nd=4), thread per row: y = A[:, :128](stride lda) @ W + b -----
// opt: if s2 != nullptr also writes |y|^2 (used for lin_s); for fc4, s2 == nullptr.
__global__ __launch_bounds__(256) void thin_kernel(
    const float* __restrict__ A, int lda,
    const float* __restrict__ Wg,     // [128, 4]
    const float* __restrict__ bg,
    float4* __restrict__ y, float* __restrict__ s2)
{
    __shared__ float4 Ws[128];
    const int tid = threadIdx.x;
    if (tid < 128) Ws[tid] = ((const float4*)Wg)[tid];
    __syncthreads();

    const int row = blockIdx.x * 256 + tid;
    const float4* xr = (const float4*)(A + (long)row * lda);
    float4 acc = make_float4(bg[0], bg[1], bg[2], bg[3]);
#pragma unroll
    for (int k4 = 0; k4 < 32; k4++) {
        float4 xv = xr[k4];
        float4 w0 = Ws[k4 * 4 + 0];
        float4 w1 = Ws[k4 * 4 + 1];
        float4 w2 = Ws[k4 * 4 + 2];
        float4 w3 = Ws[k4 * 4 + 3];
        acc.x = fmaf(xv.x, w0.x, acc.x); acc.y = fmaf(xv.x, w0.y, acc.y);
        acc.z = fmaf(xv.x, w0.z, acc.z); acc.w = fmaf(xv.x, w0.w, acc.w);
        acc.x = fmaf(xv.y, w1.x, acc.x); acc.y = fmaf(xv.y, w1.y, acc.y);
        acc.z = fmaf(xv.y, w1.z, acc.z); acc.w = fmaf(xv.y, w1.w, acc.w);
        acc.x = fmaf(xv.z, w2.x, acc.x); acc.y = fmaf(xv.z, w2.y, acc.y);
        acc.z = fmaf(xv.z, w2.z, acc.z); acc.w = fmaf(xv.z, w2.w, acc.w);
        acc.x = fmaf(xv.w, w3.x, acc.x); acc.y = fmaf(xv.w, w3.y, acc.y);
        acc.z = fmaf(xv.w, w3.z, acc.z); acc.w = fmaf(xv.w, w3.w, acc.w);
    }
    y[row] = acc;
    if (s2) s2[row] = acc.x * acc.x + acc.y * acc.y + acc.z * acc.z + acc.w * acc.w;
}

// ---------------- kNN: warp per query, warp-distributed sorted top-64 ------------
// (R3 proven version) Queue: 64 ranks, 2/lane, ascending. e = d2 - s2i.
__global__ __launch_bounds__(WPB * 32) void knn_kernel(
    const float4* __restrict__ s, const float* __restrict__ s2,
    float* __restrict__ kd, int* __restrict__ kj)
{
    __shared__ float4 sj[TJ];
    __shared__ float  s2j[TJ];

    const unsigned F = 0xffffffffu;
    const int lane = threadIdx.x & 31;
    const int warp = threadIdx.x >> 5;
    const int q    = blockIdx.x * WPB + warp;

    const float4 si = s[q];
    const float s2i = s2[q];
    const float m2x = -2.f * si.x, m2y = -2.f * si.y;
    const float m2z = -2.f * si.z, m2w = -2.f * si.w;

    float q0v = FLT_MAX, q1v = FLT_MAX;
    int   q0j = 0,       q1j = 0;
    float thrE = FLT_MAX;

    for (int t0 = 0; t0 < NQ; t0 += TJ) {
        __syncthreads();
        sj[threadIdx.x]  = s[t0 + threadIdx.x];
        s2j[threadIdx.x] = s2[t0 + threadIdx.x];
        __syncthreads();

        for (int it = 0; it < TJ / 32; it++) {
            const int ci = it * 32 + lane;
            float4 c = sj[ci];
            float e = fmaf(m2x, c.x,
                      fmaf(m2y, c.y,
                      fmaf(m2z, c.z,
                      fmaf(m2w, c.w, s2j[ci]))));
            unsigned m = __ballot_sync(F, e < thrE);
            if (m) {
                do {
                    const int src = __ffs(m) - 1; m &= m - 1;
                    const float v = __shfl_sync(F, e, src);
                    const int   j = t0 + it * 32 + src;
                    unsigned b0 = __ballot_sync(F, q0v < v);
                    unsigned b1 = __ballot_sync(F, q1v < v);
                    const int p = __popc(b0) + __popc(b1);
                    float s0v = __shfl_up_sync(F, q0v, 1);
                    int   s0j = __shfl_up_sync(F, q0j, 1);
                    float s1v = __shfl_up_sync(F, q1v, 1);
                    int   s1j = __shfl_up_sync(F, q1j, 1);
                    const float w31v = __shfl_sync(F, q0v, 31);
                    const int   w31j = __shfl_sync(F, q0j, 31);
                    if (lane == 0) { s1v = w31v; s1j = w31j; }
                    const int r1 = 32 + lane;
                    if (lane == p)      { q0v = v;   q0j = j;   }
                    else if (lane > p)  { q0v = s0v; q0j = s0j; }
                    if (r1 == p)        { q1v = v;   q1j = j;   }
                    else if (r1 > p)    { q1v = s1v; q1j = s1j; }
                } while (m);
                thrE = __shfl_sync(F, q1v, 7);   // rank 39
            }
        }
    }

    kd[q * KNN + lane] = q0v + s2i;
    kj[q * KNN + lane] = q0j;
    if (lane < KNN - 32) {
        kd[q * KNN + 32 + lane] = q1v + s2i;
        kj[q * KNN + 32 + lane] = q1j;
    }
}

// ---------------- aggregate: warp per query, mean||max of h[idx]*w ---------------
__global__ void aggregate_kernel(
    const float* __restrict__ h, const float* __restrict__ kd,
    const int* __restrict__ kj, float* __restrict__ xcat)
{
    int gw   = (blockIdx.x * blockDim.x + threadIdx.x) >> 5;  // query
    int lane = threadIdx.x & 31;

    const float* dd = kd + gw * KNN;
    const int*   jj = kj + gw * KNN;

    float m0 = 0.f, m1 = 0.f;
    float x0 = -FLT_MAX, x1 = -FLT_MAX;
#pragma unroll
    for (int k = 0; k < KNN; k++) {
        int   j = jj[k];
        float w = expf(-10.f * fmaxf(dd[k], 0.f));
        float v0 = h[j * PROP + lane] * w;
        float v1 = h[j * PROP + 32 + lane] * w;
        m0 += v0; m1 += v1;
        x0 = fmaxf(x0, v0); x1 = fmaxf(x1, v1);
    }
    float* out = xcat + (long)gw * 256 + 128;
    const float inv = 1.f / (float)KNN;
    out[lane]      = m0 * inv;
    out[32 + lane] = m1 * inv;
    out[64 + lane] = x0;
    out[96 + lane] = x1;
}

// =================================================================================
extern "C" void kernel_launch(void* const* d_in, const int* in_sizes, int n_in,
                              void* d_out, int out_size)
{
    const float* x    = (const float*)d_in[0];
    const float* fc1W = (const float*)d_in[1];
    const float* fc1b = (const float*)d_in[2];
    const float* fc2W = (const float*)d_in[3];
    const float* fc2b = (const float*)d_in[4];
    const float* gsW  = (const float*)d_in[5];
    const float* gsb  = (const float*)d_in[6];
    const float* ghW  = (const float*)d_in[7];
    const float* ghb  = (const float*)d_in[8];
    const float* goW  = (const float*)d_in[9];
    const float* gob  = (const float*)d_in[10];
    const float* d1W  = (const float*)d_in[11];
    const float* d1b  = (const float*)d_in[12];
    const float* d2W  = (const float*)d_in[13];
    const float* d2b  = (const float*)d_in[14];
    const float* d3W  = (const float*)d_in[15];
    const float* d3b  = (const float*)d_in[16];
    const float* fc3W = (const float*)d_in[17];
    const float* fc3b = (const float*)d_in[18];
    const float* fc4W = (const float*)d_in[19];
    const float* fc4b = (const float*)d_in[20];
    float* out = (float*)d_out;

    float *t1, *t2, *xcat, *xg, *s, *s2n, *h, *kd;
    int *kj;
    cudaGetSymbolAddress((void**)&t1,   g_t1);
    cudaGetSymbolAddress((void**)&t2,   g_t2);
    cudaGetSymbolAddress((void**)&xcat, g_xcat);
    cudaGetSymbolAddress((void**)&xg,   g_xg);
    cudaGetSymbolAddress((void**)&s,    g_s);
    cudaGetSymbolAddress((void**)&s2n,  g_s2);
    cudaGetSymbolAddress((void**)&h,    g_h);
    cudaGetSymbolAddress((void**)&kd,   g_kd);
    cudaGetSymbolAddress((void**)&kj,   g_kj);

    const int GB = NQ / 64;  // gemm grid

    gemm_kernel<<<GB, 256>>>(x, 9, fc1W, fc1b, t1, HID, 9, HID, 1);
    gemm_kernel<<<GB, 256>>>(t1, HID, fc2W, fc2b, xcat, 256, HID, HID, 1);

    for (int l = 0; l < 4; l++) {
        thin_kernel<<<NQ / 256, 256>>>(xcat, 256, gsW + l * HID * SPACE,
                                       gsb + l * SPACE, (float4*)s, s2n);
        gemm_kernel<<<GB, 256>>>(xcat, 256, ghW + l * HID * PROP, ghb + l * PROP,
                                 h, PROP, HID, PROP, 0);
        knn_kernel<<<NQ / WPB, WPB * 32>>>((const float4*)s, s2n, kd, kj);
        aggregate_kernel<<<NQ / 8, 256>>>(h, kd, kj, xcat);
        gemm_kernel<<<GB, 256>>>(xcat, 256, goW + l * 256 * HID, gob + l * HID,
                                 xg, HID, 256, HID, 0);
        gemm_kernel<<<GB, 256>>>(xg, HID, d1W + l * HID * HID, d1b + l * HID,
                                 t1, HID, HID, HID, 1);
        gemm_kernel<<<GB, 256>>>(t1, HID, d2W + l * HID * HID, d2b + l * HID,
                                 t2, HID, HID, HID, 1);
        gemm_kernel<<<GB, 256>>>(t2, HID, d3W + l * HID * HID, d3b + l * HID,
                                 xcat, 256, HID, HID, 1);
    }

    gemm_kernel<<<GB, 256>>>(xcat, 256, fc3W, fc3b, t1, HID, HID, HID, 1);
    thin_kernel<<<NQ / 256, 256>>>(t1, HID, fc4W, fc4b, (float4*)out, nullptr);
}

// round 9
// speedup vs baseline: 1.1922x; 1.0152x over previous
#include <cuda_runtime.h>
#include <float.h>

#define NQ    16384
#define HID   128
#define PROP  64
#define SPACE 4
#define KNN   40
#define TJ    512            // candidate tile in smem (knn)
#define WPB   8              // warps per knn block
#define WQ    4              // queries per warp

// ---------------- scratch (device globals; no allocation allowed) ----------------
__device__ float g_t1[NQ * HID];
__device__ float g_t2[NQ * HID];
__device__ float g_xcat[NQ * 256];     // [x (128) | agg_mean (64) | agg_max (64)]
__device__ float g_xg[NQ * HID];
__device__ float g_s[NQ * SPACE];
__device__ float g_s2[NQ];
__device__ float g_h[NQ * PROP];
__device__ float g_kd[NQ * KNN];
__device__ int   g_kj[NQ * KNN];

// ---------------- generic fp32 GEMM, double-buffered ------------------------------
// C = act(A[M,Kd] @ W[Kd,Nd] + b). BM=64, BN=128, BK=16, 256 thr, tile 8x4.
__global__ __launch_bounds__(256) void gemm_kernel(
    const float* __restrict__ A, int lda,
    const float* __restrict__ W,          // row-major [Kd, Nd]
    const float* __restrict__ bias,
    float* __restrict__ C, int ldc,
    int Kd, int Nd, int relu)
{
    __shared__ float As[2][64][16];
    __shared__ float Bs[2][16][128];

    const int tid = threadIdx.x;
    const int m0  = blockIdx.x * 64;
    const int tn  = tid & 31;
    const int tm  = tid >> 5;
    const int arow = tid >> 2;
    const int ak   = (tid & 3) * 4;
    const int bn   = (tid & 31) * 4;
    const int bk   = tid >> 5;

    float acc[8][4];
#pragma unroll
    for (int i = 0; i < 8; i++)
#pragma unroll
        for (int j = 0; j < 4; j++) acc[i][j] = 0.f;

    float4 av, bv0, bv1;

#define GEMM_LDG(K0)                                                      \
    {                                                                     \
        const float* ap = A + (long)(m0 + arow) * lda + (K0) + ak;        \
        av.x = ((K0) + ak + 0 < Kd) ? ap[0] : 0.f;                        \
        av.y = ((K0) + ak + 1 < Kd) ? ap[1] : 0.f;                        \
        av.z = ((K0) + ak + 2 < Kd) ? ap[2] : 0.f;                        \
        av.w = ((K0) + ak + 3 < Kd) ? ap[3] : 0.f;                        \
        bv0 = make_float4(0.f, 0.f, 0.f, 0.f);                            \
        bv1 = make_float4(0.f, 0.f, 0.f, 0.f);                            \
        if ((K0) + bk < Kd) {                                             \
            const float* wp = W + (long)((K0) + bk) * Nd + bn;            \
            if (bn + 0 < Nd) bv0.x = wp[0];                               \
            if (bn + 1 < Nd) bv0.y = wp[1];                               \
            if (bn + 2 < Nd) bv0.z = wp[2];                               \
            if (bn + 3 < Nd) bv0.w = wp[3];                               \
        }                                                                 \
        if ((K0) + bk + 8 < Kd) {                                         \
            const float* wp = W + (long)((K0) + bk + 8) * Nd + bn;        \
            if (bn + 0 < Nd) bv1.x = wp[0];                               \
            if (bn + 1 < Nd) bv1.y = wp[1];                               \
            if (bn + 2 < Nd) bv1.z = wp[2];                               \
            if (bn + 3 < Nd) bv1.w = wp[3];                               \
        }                                                                 \
    }

#define GEMM_STS(BUF)                                                     \
    {                                                                     \
        *(float4*)&As[BUF][arow][ak]   = av;                              \
        *(float4*)&Bs[BUF][bk][bn]     = bv0;                             \
        *(float4*)&Bs[BUF][bk + 8][bn] = bv1;                             \
    }

    const int nT = (Kd + 15) / 16;
    GEMM_LDG(0);
    GEMM_STS(0);
    __syncthreads();

    for (int t = 0; t < nT; t++) {
        const int cur = t & 1;
        if (t + 1 < nT) GEMM_LDG((t + 1) * 16);

#pragma unroll
        for (int kk4 = 0; kk4 < 16; kk4 += 4) {
            float4 b0 = *(const float4*)&Bs[cur][kk4 + 0][tn * 4];
            float4 b1 = *(const float4*)&Bs[cur][kk4 + 1][tn * 4];
            float4 b2 = *(const float4*)&Bs[cur][kk4 + 2][tn * 4];
            float4 b3 = *(const float4*)&Bs[cur][kk4 + 3][tn * 4];
#pragma unroll
            for (int i = 0; i < 8; i++) {
                float4 a = *(const float4*)&As[cur][tm * 8 + i][kk4];
                acc[i][0] = fmaf(a.x, b0.x, acc[i][0]);
                acc[i][1] = fmaf(a.x, b0.y, acc[i][1]);
                acc[i][2] = fmaf(a.x, b0.z, acc[i][2]);
                acc[i][3] = fmaf(a.x, b0.w, acc[i][3]);
                acc[i][0] = fmaf(a.y, b1.x, acc[i][0]);
                acc[i][1] = fmaf(a.y, b1.y, acc[i][1]);
                acc[i][2] = fmaf(a.y, b1.z, acc[i][2]);
                acc[i][3] = fmaf(a.y, b1.w, acc[i][3]);
                acc[i][0] = fmaf(a.z, b2.x, acc[i][0]);
                acc[i][1] = fmaf(a.z, b2.y, acc[i][1]);
                acc[i][2] = fmaf(a.z, b2.z, acc[i][2]);
                acc[i][3] = fmaf(a.z, b2.w, acc[i][3]);
                acc[i][0] = fmaf(a.w, b3.x, acc[i][0]);
                acc[i][1] = fmaf(a.w, b3.y, acc[i][1]);
                acc[i][2] = fmaf(a.w, b3.z, acc[i][2]);
                acc[i][3] = fmaf(a.w, b3.w, acc[i][3]);
            }
        }

        if (t + 1 < nT) GEMM_STS(cur ^ 1);
        __syncthreads();
    }

#pragma unroll
    for (int i = 0; i < 8; i++) {
        int row = m0 + tm * 8 + i;
#pragma unroll
        for (int j = 0; j < 4; j++) {
            int col = tn * 4 + j;
            if (col < Nd) {
                float v = acc[i][j] + bias[col];
                if (relu) v = fmaxf(v, 0.f);
                C[(long)row * ldc + col] = v;
            }
        }
    }
}

// ------- thin GEMM (Nd=4), thread per row: y = A[:, :128](stride lda) @ W + b -----
__global__ __launch_bounds__(256) void thin_kernel(
    const float* __restrict__ A, int lda,
    const float* __restrict__ Wg,     // [128, 4]
    const float* __restrict__ bg,
    float4* __restrict__ y, float* __restrict__ s2)
{
    __shared__ float4 Ws[128];
    const int tid = threadIdx.x;
    if (tid < 128) Ws[tid] = ((const float4*)Wg)[tid];
    __syncthreads();

    const int row = blockIdx.x * 256 + tid;
    const float4* xr = (const float4*)(A + (long)row * lda);
    float4 acc = make_float4(bg[0], bg[1], bg[2], bg[3]);
#pragma unroll
    for (int k4 = 0; k4 < 32; k4++) {
        float4 xv = xr[k4];
        float4 w0 = Ws[k4 * 4 + 0];
        float4 w1 = Ws[k4 * 4 + 1];
        float4 w2 = Ws[k4 * 4 + 2];
        float4 w3 = Ws[k4 * 4 + 3];
        acc.x = fmaf(xv.x, w0.x, acc.x); acc.y = fmaf(xv.x, w0.y, acc.y);
        acc.z = fmaf(xv.x, w0.z, acc.z); acc.w = fmaf(xv.x, w0.w, acc.w);
        acc.x = fmaf(xv.y, w1.x, acc.x); acc.y = fmaf(xv.y, w1.y, acc.y);
        acc.z = fmaf(xv.y, w1.z, acc.z); acc.w = fmaf(xv.y, w1.w, acc.w);
        acc.x = fmaf(xv.z, w2.x, acc.x); acc.y = fmaf(xv.z, w2.y, acc.y);
        acc.z = fmaf(xv.z, w2.z, acc.z); acc.w = fmaf(xv.z, w2.w, acc.w);
        acc.x = fmaf(xv.w, w3.x, acc.x); acc.y = fmaf(xv.w, w3.y, acc.y);
        acc.z = fmaf(xv.w, w3.z, acc.z); acc.w = fmaf(xv.w, w3.w, acc.w);
    }
    y[row] = acc;
    if (s2) s2[row] = acc.x * acc.x + acc.y * acc.y + acc.z * acc.z + acc.w * acc.w;
}

// ---------------- kNN: 4 queries per warp, warp-distributed sorted top-64 --------
// Candidate tiles in smem are shared by all 4 queries -> smem crossbar traffic /4.
// Queue per query: 64 ranks, 2/lane, ascending. e = d2 - s2i.
__global__ __launch_bounds__(WPB * 32) void knn_kernel(
    const float4* __restrict__ s, const float* __restrict__ s2,
    float* __restrict__ kd, int* __restrict__ kj)
{
    __shared__ float4 sj[TJ];
    __shared__ float  s2j[TJ];

    const unsigned F = 0xffffffffu;
    const int tid  = threadIdx.x;
    const int lane = tid & 31;
    const int warp = tid >> 5;
    const int qb   = (blockIdx.x * WPB + warp) * WQ;

    float m2x[WQ], m2y[WQ], m2z[WQ], m2w[WQ], s2i[WQ];
    float q0v[WQ], q1v[WQ], thrE[WQ];
    int   q0j[WQ], q1j[WQ];

#pragma unroll
    for (int u = 0; u < WQ; u++) {
        float4 si = s[qb + u];
        s2i[u] = s2[qb + u];
        m2x[u] = -2.f * si.x; m2y[u] = -2.f * si.y;
        m2z[u] = -2.f * si.z; m2w[u] = -2.f * si.w;
        q0v[u] = FLT_MAX; q1v[u] = FLT_MAX;
        q0j[u] = 0;       q1j[u] = 0;
        thrE[u] = FLT_MAX;
    }

    for (int t0 = 0; t0 < NQ; t0 += TJ) {
        __syncthreads();
        sj[tid]        = s[t0 + tid];
        sj[tid + 256]  = s[t0 + tid + 256];
        s2j[tid]       = s2[t0 + tid];
        s2j[tid + 256] = s2[t0 + tid + 256];
        __syncthreads();

        for (int it = 0; it < TJ / 32; it++) {
            const int ci = it * 32 + lane;
            const float4 c  = sj[ci];
            const float  cz = s2j[ci];
#pragma unroll
            for (int u = 0; u < WQ; u++) {
                float e = fmaf(m2x[u], c.x,
                          fmaf(m2y[u], c.y,
                          fmaf(m2z[u], c.z,
                          fmaf(m2w[u], c.w, cz))));
                unsigned m = __ballot_sync(F, e < thrE[u]);
                if (m) {
                    do {
                        const int src = __ffs(m) - 1; m &= m - 1;
                        const float v = __shfl_sync(F, e, src);
                        const int   j = t0 + it * 32 + src;
                        unsigned b0 = __ballot_sync(F, q0v[u] < v);
                        unsigned b1 = __ballot_sync(F, q1v[u] < v);
                        const int p = __popc(b0) + __popc(b1);
                        float s0v = __shfl_up_sync(F, q0v[u], 1);
                        int   s0j = __shfl_up_sync(F, q0j[u], 1);
                        float s1v = __shfl_up_sync(F, q1v[u], 1);
                        int   s1j = __shfl_up_sync(F, q1j[u], 1);
                        const float w31v = __shfl_sync(F, q0v[u], 31);
                        const int   w31j = __shfl_sync(F, q0j[u], 31);
                        if (lane == 0) { s1v = w31v; s1j = w31j; }
                        const int r1 = 32 + lane;
                        if (lane == p)      { q0v[u] = v;   q0j[u] = j;   }
                        else if (lane > p)  { q0v[u] = s0v; q0j[u] = s0j; }
                        if (r1 == p)        { q1v[u] = v;   q1j[u] = j;   }
                        else if (r1 > p)    { q1v[u] = s1v; q1j[u] = s1j; }
                    } while (m);
                    thrE[u] = __shfl_sync(F, q1v[u], 7);   // rank 39
                }
            }
        }
    }

#pragma unroll
    for (int u = 0; u < WQ; u++) {
        const int q = qb + u;
        kd[q * KNN + lane] = q0v[u] + s2i[u];
        kj[q * KNN + lane] = q0j[u];
        if (lane < KNN - 32) {
            kd[q * KNN + 32 + lane] = q1v[u] + s2i[u];
            kj[q * KNN + 32 + lane] = q1j[u];
        }
    }
}

// ---------------- aggregate: warp per query, mean||max of h[idx]*w ---------------
__global__ void aggregate_kernel(
    const float* __restrict__ h, const float* __restrict__ kd,
    const int* __restrict__ kj, float* __restrict__ xcat)
{
    int gw   = (blockIdx.x * blockDim.x + threadIdx.x) >> 5;  // query
    int lane = threadIdx.x & 31;

    const float* dd = kd + gw * KNN;
    const int*   jj = kj + gw * KNN;

    float m0 = 0.f, m1 = 0.f;
    float x0 = -FLT_MAX, x1 = -FLT_MAX;
#pragma unroll
    for (int k = 0; k < KNN; k++) {
        int   j = jj[k];
        float w = expf(-10.f * fmaxf(dd[k], 0.f));
        float v0 = h[j * PROP + lane] * w;
        float v1 = h[j * PROP + 32 + lane] * w;
        m0 += v0; m1 += v1;
        x0 = fmaxf(x0, v0); x1 = fmaxf(x1, v1);
    }
    float* out = xcat + (long)gw * 256 + 128;
    const float inv = 1.f / (float)KNN;
    out[lane]      = m0 * inv;
    out[32 + lane] = m1 * inv;
    out[64 + lane] = x0;
    out[96 + lane] = x1;
}

// =================================================================================
extern "C" void kernel_launch(void* const* d_in, const int* in_sizes, int n_in,
                              void* d_out, int out_size)
{
    const float* x    = (const float*)d_in[0];
    const float* fc1W = (const float*)d_in[1];
    const float* fc1b = (const float*)d_in[2];
    const float* fc2W = (const float*)d_in[3];
    const float* fc2b = (const float*)d_in[4];
    const float* gsW  = (const float*)d_in[5];
    const float* gsb  = (const float*)d_in[6];
    const float* ghW  = (const float*)d_in[7];
    const float* ghb  = (const float*)d_in[8];
    const float* goW  = (const float*)d_in[9];
    const float* gob  = (const float*)d_in[10];
    const float* d1W  = (const float*)d_in[11];
    const float* d1b  = (const float*)d_in[12];
    const float* d2W  = (const float*)d_in[13];
    const float* d2b  = (const float*)d_in[14];
    const float* d3W  = (const float*)d_in[15];
    const float* d3b  = (const float*)d_in[16];
    const float* fc3W = (const float*)d_in[17];
    const float* fc3b = (const float*)d_in[18];
    const float* fc4W = (const float*)d_in[19];
    const float* fc4b = (const float*)d_in[20];
    float* out = (float*)d_out;

    float *t1, *t2, *xcat, *xg, *s, *s2n, *h, *kd;
    int *kj;
    cudaGetSymbolAddress((void**)&t1,   g_t1);
    cudaGetSymbolAddress((void**)&t2,   g_t2);
    cudaGetSymbolAddress((void**)&xcat, g_xcat);
    cudaGetSymbolAddress((void**)&xg,   g_xg);
    cudaGetSymbolAddress((void**)&s,    g_s);
    cudaGetSymbolAddress((void**)&s2n,  g_s2);
    cudaGetSymbolAddress((void**)&h,    g_h);
    cudaGetSymbolAddress((void**)&kd,   g_kd);
    cudaGetSymbolAddress((void**)&kj,   g_kj);

    const int GB = NQ / 64;  // gemm grid

    gemm_kernel<<<GB, 256>>>(x, 9, fc1W, fc1b, t1, HID, 9, HID, 1);
    gemm_kernel<<<GB, 256>>>(t1, HID, fc2W, fc2b, xcat, 256, HID, HID, 1);

    for (int l = 0; l < 4; l++) {
        thin_kernel<<<NQ / 256, 256>>>(xcat, 256, gsW + l * HID * SPACE,
                                       gsb + l * SPACE, (float4*)s, s2n);
        gemm_kernel<<<GB, 256>>>(xcat, 256, ghW + l * HID * PROP, ghb + l * PROP,
                                 h, PROP, HID, PROP, 0);
        knn_kernel<<<NQ / (WPB * WQ), WPB * 32>>>((const float4*)s, s2n, kd, kj);
        aggregate_kernel<<<NQ / 8, 256>>>(h, kd, kj, xcat);
        gemm_kernel<<<GB, 256>>>(xcat, 256, goW + l * 256 * HID, gob + l * HID,
                                 xg, HID, 256, HID, 0);
        gemm_kernel<<<GB, 256>>>(xg, HID, d1W + l * HID * HID, d1b + l * HID,
                                 t1, HID, HID, HID, 1);
        gemm_kernel<<<GB, 256>>>(t1, HID, d2W + l * HID * HID, d2b + l * HID,
                                 t2, HID, HID, HID, 1);
        gemm_kernel<<<GB, 256>>>(t2, HID, d3W + l * HID * HID, d3b + l * HID,
                                 xcat, 256, HID, HID, 1);
    }

    gemm_kernel<<<GB, 256>>>(xcat, 256, fc3W, fc3b, t1, HID, HID, HID, 1);
    thin_kernel<<<NQ / 256, 256>>>(t1, HID, fc4W, fc4b, (float4*)out, nullptr);
}

// round 11
// speedup vs baseline: 1.2439x; 1.0434x over previous
#include <cuda_runtime.h>
#include <float.h>

#define NQ    16384
#define HID   128
#define PROP  64
#define SPACE 4
#define KNN   40
#define TJ    512            // candidate tile in smem (knn)
#define WPB   8              // warps per knn block
#define WQ    4              // queries per warp

// ---------------- scratch (device globals; no allocation allowed) ----------------
__device__ float g_t1[NQ * HID];
__device__ float g_t2[NQ * HID];
__device__ float g_xcat[NQ * 256];     // [x (128) | agg_mean (64) | agg_max (64)]
__device__ float g_xg[NQ * HID];
__device__ float g_s[NQ * SPACE];
__device__ float g_s2[NQ];
__device__ float g_h[NQ * PROP];
__device__ float g_kd[NQ * KNN];
__device__ int   g_kj[NQ * KNN];

// ---------------- generic fp32 GEMM, double-buffered ------------------------------
// C = act(A[M,Kd] @ W[Kd,Nd] + b). BM=64, BN=128, BK=16, 256 thr, tile 8x4.
__global__ __launch_bounds__(256) void gemm_kernel(
    const float* __restrict__ A, int lda,
    const float* __restrict__ W,          // row-major [Kd, Nd]
    const float* __restrict__ bias,
    float* __restrict__ C, int ldc,
    int Kd, int Nd, int relu)
{
    __shared__ float As[2][64][16];
    __shared__ float Bs[2][16][128];

    const int tid = threadIdx.x;
    const int m0  = blockIdx.x * 64;
    const int tn  = tid & 31;
    const int tm  = tid >> 5;
    const int arow = tid >> 2;
    const int ak   = (tid & 3) * 4;
    const int bn   = (tid & 31) * 4;
    const int bk   = tid >> 5;

    float acc[8][4];
#pragma unroll
    for (int i = 0; i < 8; i++)
#pragma unroll
        for (int j = 0; j < 4; j++) acc[i][j] = 0.f;

    float4 av, bv0, bv1;

#define GEMM_LDG(K0)                                                      \
    {                                                                     \
        const float* ap = A + (long)(m0 + arow) * lda + (K0) + ak;        \
        av.x = ((K0) + ak + 0 < Kd) ? ap[0] : 0.f;                        \
        av.y = ((K0) + ak + 1 < Kd) ? ap[1] : 0.f;                        \
        av.z = ((K0) + ak + 2 < Kd) ? ap[2] : 0.f;                        \
        av.w = ((K0) + ak + 3 < Kd) ? ap[3] : 0.f;                        \
        bv0 = make_float4(0.f, 0.f, 0.f, 0.f);                            \
        bv1 = make_float4(0.f, 0.f, 0.f, 0.f);                            \
        if ((K0) + bk < Kd) {                                             \
            const float* wp = W + (long)((K0) + bk) * Nd + bn;            \
            if (bn + 0 < Nd) bv0.x = wp[0];                               \
            if (bn + 1 < Nd) bv0.y = wp[1];                               \
            if (bn + 2 < Nd) bv0.z = wp[2];                               \
            if (bn + 3 < Nd) bv0.w = wp[3];                               \
        }                                                                 \
        if ((K0) + bk + 8 < Kd) {                                         \
            const float* wp = W + (long)((K0) + bk + 8) * Nd + bn;        \
            if (bn + 0 < Nd) bv1.x = wp[0];                               \
            if (bn + 1 < Nd) bv1.y = wp[1];                               \
            if (bn + 2 < Nd) bv1.z = wp[2];                               \
            if (bn + 3 < Nd) bv1.w = wp[3];                               \
        }                                                                 \
    }

#define GEMM_STS(BUF)                                                     \
    {                                                                     \
        *(float4*)&As[BUF][arow][ak]   = av;                              \
        *(float4*)&Bs[BUF][bk][bn]     = bv0;                             \
        *(float4*)&Bs[BUF][bk + 8][bn] = bv1;                             \
    }

    const int nT = (Kd + 15) / 16;
    GEMM_LDG(0);
    GEMM_STS(0);
    __syncthreads();

    for (int t = 0; t < nT; t++) {
        const int cur = t & 1;
        if (t + 1 < nT) GEMM_LDG((t + 1) * 16);

#pragma unroll
        for (int kk4 = 0; kk4 < 16; kk4 += 4) {
            float4 b0 = *(const float4*)&Bs[cur][kk4 + 0][tn * 4];
            float4 b1 = *(const float4*)&Bs[cur][kk4 + 1][tn * 4];
            float4 b2 = *(const float4*)&Bs[cur][kk4 + 2][tn * 4];
            float4 b3 = *(const float4*)&Bs[cur][kk4 + 3][tn * 4];
#pragma unroll
            for (int i = 0; i < 8; i++) {
                float4 a = *(const float4*)&As[cur][tm * 8 + i][kk4];
                acc[i][0] = fmaf(a.x, b0.x, acc[i][0]);
                acc[i][1] = fmaf(a.x, b0.y, acc[i][1]);
                acc[i][2] = fmaf(a.x, b0.z, acc[i][2]);
                acc[i][3] = fmaf(a.x, b0.w, acc[i][3]);
                acc[i][0] = fmaf(a.y, b1.x, acc[i][0]);
                acc[i][1] = fmaf(a.y, b1.y, acc[i][1]);
                acc[i][2] = fmaf(a.y, b1.z, acc[i][2]);
                acc[i][3] = fmaf(a.y, b1.w, acc[i][3]);
                acc[i][0] = fmaf(a.z, b2.x, acc[i][0]);
                acc[i][1] = fmaf(a.z, b2.y, acc[i][1]);
                acc[i][2] = fmaf(a.z, b2.z, acc[i][2]);
                acc[i][3] = fmaf(a.z, b2.w, acc[i][3]);
                acc[i][0] = fmaf(a.w, b3.x, acc[i][0]);
                acc[i][1] = fmaf(a.w, b3.y, acc[i][1]);
                acc[i][2] = fmaf(a.w, b3.z, acc[i][2]);
                acc[i][3] = fmaf(a.w, b3.w, acc[i][3]);
            }
        }

        if (t + 1 < nT) GEMM_STS(cur ^ 1);
        __syncthreads();
    }

#pragma unroll
    for (int i = 0; i < 8; i++) {
        int row = m0 + tm * 8 + i;
#pragma unroll
        for (int j = 0; j < 4; j++) {
            int col = tn * 4 + j;
            if (col < Nd) {
                float v = acc[i][j] + bias[col];
                if (relu) v = fmaxf(v, 0.f);
                C[(long)row * ldc + col] = v;
            }
        }
    }
}

// ------- thin GEMM (Nd=4), thread per row: y = A[:, :128](stride lda) @ W + b -----
__global__ __launch_bounds__(256) void thin_kernel(
    const float* __restrict__ A, int lda,
    const float* __restrict__ Wg,     // [128, 4]
    const float* __restrict__ bg,
    float4* __restrict__ y, float* __restrict__ s2)
{
    __shared__ float4 Ws[128];
    const int tid = threadIdx.x;
    if (tid < 128) Ws[tid] = ((const float4*)Wg)[tid];
    __syncthreads();

    const int row = blockIdx.x * 256 + tid;
    const float4* xr = (const float4*)(A + (long)row * lda);
    float4 acc = make_float4(bg[0], bg[1], bg[2], bg[3]);
#pragma unroll
    for (int k4 = 0; k4 < 32; k4++) {
        float4 xv = xr[k4];
        float4 w0 = Ws[k4 * 4 + 0];
        float4 w1 = Ws[k4 * 4 + 1];
        float4 w2 = Ws[k4 * 4 + 2];
        float4 w3 = Ws[k4 * 4 + 3];
        acc.x = fmaf(xv.x, w0.x, acc.x); acc.y = fmaf(xv.x, w0.y, acc.y);
        acc.z = fmaf(xv.x, w0.z, acc.z); acc.w = fmaf(xv.x, w0.w, acc.w);
        acc.x = fmaf(xv.y, w1.x, acc.x); acc.y = fmaf(xv.y, w1.y, acc.y);
        acc.z = fmaf(xv.y, w1.z, acc.z); acc.w = fmaf(xv.y, w1.w, acc.w);
        acc.x = fmaf(xv.z, w2.x, acc.x); acc.y = fmaf(xv.z, w2.y, acc.y);
        acc.z = fmaf(xv.z, w2.z, acc.z); acc.w = fmaf(xv.z, w2.w, acc.w);
        acc.x = fmaf(xv.w, w3.x, acc.x); acc.y = fmaf(xv.w, w3.y, acc.y);
        acc.z = fmaf(xv.w, w3.z, acc.z); acc.w = fmaf(xv.w, w3.w, acc.w);
    }
    y[row] = acc;
    if (s2) s2[row] = acc.x * acc.x + acc.y * acc.y + acc.z * acc.z + acc.w * acc.w;
}

// ---- tiny pad launch: positions knn_kernel as the 6th launch for ncu (-s 5 -c 1).
// Writes zeros into g_t2[0..31]; t2 is fully overwritten by a later GEMM before
// any read, so this is harmless and deterministic.
__global__ void pad_kernel(float* p) { p[threadIdx.x] = 0.f; }

// ---------------- kNN: 4 queries/warp, interleaved-rank sorted top-64 ------------
// Rank r in [0,64): lane = r>>1, slot = r&1 (q0 = even ranks, q1 = odd ranks).
// Shift-by-one on insert = 1 shfl_up (q1 -> next lane's q0) + local q0 -> q1 move.
// e-space values: e = d2 - s2i (monotone in d2).
__global__ __launch_bounds__(WPB * 32) void knn_kernel(
    const float4* __restrict__ s, const float* __restrict__ s2,
    float* __restrict__ kd, int* __restrict__ kj)
{
    __shared__ float4 sj[TJ];
    __shared__ float  s2j[TJ];

    const unsigned F = 0xffffffffu;
    const int tid  = threadIdx.x;
    const int lane = tid & 31;
    const int warp = tid >> 5;
    const int qb   = (blockIdx.x * WPB + warp) * WQ;
    const int r0   = 2 * lane;
    const int r1   = 2 * lane + 1;

    float m2x[WQ], m2y[WQ], m2z[WQ], m2w[WQ], s2i[WQ];
    float q0v[WQ], q1v[WQ], thrE[WQ];
    int   q0j[WQ], q1j[WQ];

#pragma unroll
    for (int u = 0; u < WQ; u++) {
        float4 si = s[qb + u];
        s2i[u] = s2[qb + u];
        m2x[u] = -2.f * si.x; m2y[u] = -2.f * si.y;
        m2z[u] = -2.f * si.z; m2w[u] = -2.f * si.w;
        q0v[u] = FLT_MAX; q1v[u] = FLT_MAX;
        q0j[u] = 0;       q1j[u] = 0;
        thrE[u] = FLT_MAX;
    }

    for (int t0 = 0; t0 < NQ; t0 += TJ) {
        __syncthreads();
        sj[tid]        = s[t0 + tid];
        sj[tid + 256]  = s[t0 + tid + 256];
        s2j[tid]       = s2[t0 + tid];
        s2j[tid + 256] = s2[t0 + tid + 256];
        __syncthreads();

        for (int it = 0; it < TJ / 32; it++) {
            const int ci = it * 32 + lane;
            const int jbase = t0 + it * 32;
            const float4 c  = sj[ci];
            const float  cz = s2j[ci];
#pragma unroll
            for (int u = 0; u < WQ; u++) {
                float e = fmaf(m2x[u], c.x,
                          fmaf(m2y[u], c.y,
                          fmaf(m2z[u], c.z,
                          fmaf(m2w[u], c.w, cz))));
                unsigned m = __ballot_sync(F, e < thrE[u]);
                if (m) {
                    do {
                        const int src = __ffs(m) - 1; m &= m - 1;
                        const float v = __shfl_sync(F, e, src);
                        const int   j = jbase + src;
                        // interleaved-rank cooperative insert
                        unsigned b0 = __ballot_sync(F, q0v[u] < v);
                        unsigned b1 = __ballot_sync(F, q1v[u] < v);
                        const int p = __popc(b0) + __popc(b1);
                        float s1v = __shfl_up_sync(F, q1v[u], 1);
                        int   s1j = __shfl_up_sync(F, q1j[u], 1);
                        const float oq0v = q0v[u];
                        const int   oq0j = q0j[u];
                        if (r0 == p)      { q0v[u] = v;    q0j[u] = j;    }
                        else if (r0 > p)  { q0v[u] = s1v;  q0j[u] = s1j;  }
                        if (r1 == p)      { q1v[u] = v;    q1j[u] = j;    }
                        else if (r1 > p)  { q1v[u] = oq0v; q1j[u] = oq0j; }
                    } while (m);
                    thrE[u] = __shfl_sync(F, q1v[u], 19);   // rank 39
                }
            }
        }
    }

#pragma unroll
    for (int u = 0; u < WQ; u++) {
        const int q = qb + u;
        if (lane < 20) {                       // ranks 0..39
            kd[q * KNN + r0] = q0v[u] + s2i[u];
            kj[q * KNN + r0] = q0j[u];
            kd[q * KNN + r1] = q1v[u] + s2i[u];
            kj[q * KNN + r1] = q1j[u];
        }
    }
}

// ---------------- aggregate: warp per query, mean||max of h[idx]*w ---------------
__global__ void aggregate_kernel(
    const float* __restrict__ h, const float* __restrict__ kd,
    const int* __restrict__ kj, float* __restrict__ xcat)
{
    int gw   = (blockIdx.x * blockDim.x + threadIdx.x) >> 5;  // query
    int lane = threadIdx.x & 31;

    const float* dd = kd + gw * KNN;
    const int*   jj = kj + gw * KNN;

    float m0 = 0.f, m1 = 0.f;
    float x0 = -FLT_MAX, x1 = -FLT_MAX;
#pragma unroll
    for (int k = 0; k < KNN; k++) {
        int   j = jj[k];
        float w = expf(-10.f * fmaxf(dd[k], 0.f));
        float v0 = h[j * PROP + lane] * w;
        float v1 = h[j * PROP + 32 + lane] * w;
        m0 += v0; m1 += v1;
        x0 = fmaxf(x0, v0); x1 = fmaxf(x1, v1);
    }
    float* out = xcat + (long)gw * 256 + 128;
    const float inv = 1.f / (float)KNN;
    out[lane]      = m0 * inv;
    out[32 + lane] = m1 * inv;
    out[64 + lane] = x0;
    out[96 + lane] = x1;
}

// =================================================================================
extern "C" void kernel_launch(void* const* d_in, const int* in_sizes, int n_in,
                              void* d_out, int out_size)
{
    const float* x    = (const float*)d_in[0];
    const float* fc1W = (const float*)d_in[1];
    const float* fc1b = (const float*)d_in[2];
    const float* fc2W = (const float*)d_in[3];
    const float* fc2b = (const float*)d_in[4];
    const float* gsW  = (const float*)d_in[5];
    const float* gsb  = (const float*)d_in[6];
    const float* ghW  = (const float*)d_in[7];
    const float* ghb  = (const float*)d_in[8];
    const float* goW  = (const float*)d_in[9];
    const float* gob  = (const float*)d_in[10];
    const float* d1W  = (const float*)d_in[11];
    const float* d1b  = (const float*)d_in[12];
    const float* d2W  = (const float*)d_in[13];
    const float* d2b  = (const float*)d_in[14];
    const float* d3W  = (const float*)d_in[15];
    const float* d3b  = (const float*)d_in[16];
    const float* fc3W = (const float*)d_in[17];
    const float* fc3b = (const float*)d_in[18];
    const float* fc4W = (const float*)d_in[19];
    const float* fc4b = (const float*)d_in[20];
    float* out = (float*)d_out;

    float *t1, *t2, *xcat, *xg, *s, *s2n, *h, *kd;
    int *kj;
    cudaGetSymbolAddress((void**)&t1,   g_t1);
    cudaGetSymbolAddress((void**)&t2,   g_t2);
    cudaGetSymbolAddress((void**)&xcat, g_xcat);
    cudaGetSymbolAddress((void**)&xg,   g_xg);
    cudaGetSymbolAddress((void**)&s,    g_s);
    cudaGetSymbolAddress((void**)&s2n,  g_s2);
    cudaGetSymbolAddress((void**)&h,    g_h);
    cudaGetSymbolAddress((void**)&kd,   g_kd);
    cudaGetSymbolAddress((void**)&kj,   g_kj);

    const int GB = NQ / 64;  // gemm grid

    gemm_kernel<<<GB, 256>>>(x, 9, fc1W, fc1b, t1, HID, 9, HID, 1);          // 1
    gemm_kernel<<<GB, 256>>>(t1, HID, fc2W, fc2b, xcat, 256, HID, HID, 1);   // 2

    for (int l = 0; l < 4; l++) {
        gemm_kernel<<<GB, 256>>>(xcat, 256, ghW + l * HID * PROP, ghb + l * PROP,
                                 h, PROP, HID, PROP, 0);                     // 3
        thin_kernel<<<NQ / 256, 256>>>(xcat, 256, gsW + l * HID * SPACE,
                                       gsb + l * SPACE, (float4*)s, s2n);    // 4
        if (l == 0) pad_kernel<<<1, 32>>>(t2);                               // 5
        knn_kernel<<<NQ / (WPB * WQ), WPB * 32>>>((const float4*)s, s2n, kd, kj); // 6
        aggregate_kernel<<<NQ / 8, 256>>>(h, kd, kj, xcat);
        gemm_kernel<<<GB, 256>>>(xcat, 256, goW + l * 256 * HID, gob + l * HID,
                                 xg, HID, 256, HID, 0);
        gemm_kernel<<<GB, 256>>>(xg, HID, d1W + l * HID * HID, d1b + l * HID,
                                 t1, HID, HID, HID, 1);
        gemm_kernel<<<GB, 256>>>(t1, HID, d2W + l * HID * HID, d2b + l * HID,
                                 t2, HID, HID, HID, 1);
        gemm_kernel<<<GB, 256>>>(t2, HID, d3W + l * HID * HID, d3b + l * HID,
                                 xcat, 256, HID, HID, 1);
    }

    gemm_kernel<<<GB, 256>>>(xcat, 256, fc3W, fc3b, t1, HID, HID, HID, 1);
    thin_kernel<<<NQ / 256, 256>>>(t1, HID, fc4W, fc4b, (float4*)out, nullptr);
}

// round 12
// speedup vs baseline: 1.2618x; 1.0144x over previous
#include <cuda_runtime.h>
#include <float.h>

#define NQ    16384
#define HID   128
#define PROP  64
#define SPACE 4
#define KNN   40
#define TJ    512            // candidate tile in smem (knn)
#define WPB   8              // warps per knn block
#define WQ    4              // queries per warp

// ---------------- scratch (device globals; no allocation allowed) ----------------
__device__ float g_t1[NQ * HID];
__device__ float g_t2[NQ * HID];
__device__ float g_xcat[NQ * 256];     // [x (128) | agg_mean (64) | agg_max (64)]
__device__ float g_xg[NQ * HID];
__device__ float g_s[NQ * SPACE];
__device__ float g_s2[NQ];
__device__ float g_h[NQ * PROP];
__device__ float g_kd[NQ * KNN];
__device__ int   g_kj[NQ * KNN];

// ---------------- generic fp32 GEMM, double-buffered ------------------------------
// C = act(A[M,Kd] @ W[Kd,Nd] + b). BM=64, BN=128, BK=16, 256 thr, tile 8x4.
__global__ __launch_bounds__(256) void gemm_kernel(
    const float* __restrict__ A, int lda,
    const float* __restrict__ W,          // row-major [Kd, Nd]
    const float* __restrict__ bias,
    float* __restrict__ C, int ldc,
    int Kd, int Nd, int relu)
{
    __shared__ float As[2][64][16];
    __shared__ float Bs[2][16][128];

    const int tid = threadIdx.x;
    const int m0  = blockIdx.x * 64;
    const int tn  = tid & 31;
    const int tm  = tid >> 5;
    const int arow = tid >> 2;
    const int ak   = (tid & 3) * 4;
    const int bn   = (tid & 31) * 4;
    const int bk   = tid >> 5;

    float acc[8][4];
#pragma unroll
    for (int i = 0; i < 8; i++)
#pragma unroll
        for (int j = 0; j < 4; j++) acc[i][j] = 0.f;

    float4 av, bv0, bv1;

#define GEMM_LDG(K0)                                                      \
    {                                                                     \
        const float* ap = A + (long)(m0 + arow) * lda + (K0) + ak;        \
        av.x = ((K0) + ak + 0 < Kd) ? ap[0] : 0.f;                        \
        av.y = ((K0) + ak + 1 < Kd) ? ap[1] : 0.f;                        \
        av.z = ((K0) + ak + 2 < Kd) ? ap[2] : 0.f;                        \
        av.w = ((K0) + ak + 3 < Kd) ? ap[3] : 0.f;                        \
        bv0 = make_float4(0.f, 0.f, 0.f, 0.f);                            \
        bv1 = make_float4(0.f, 0.f, 0.f, 0.f);                            \
        if ((K0) + bk < Kd) {                                             \
            const float* wp = W + (long)((K0) + bk) * Nd + bn;            \
            if (bn + 0 < Nd) bv0.x = wp[0];                               \
            if (bn + 1 < Nd) bv0.y = wp[1];                               \
            if (bn + 2 < Nd) bv0.z = wp[2];                               \
            if (bn + 3 < Nd) bv0.w = wp[3];                               \
        }                                                                 \
        if ((K0) + bk + 8 < Kd) {                                         \
            const float* wp = W + (long)((K0) + bk + 8) * Nd + bn;        \
            if (bn + 0 < Nd) bv1.x = wp[0];                               \
            if (bn + 1 < Nd) bv1.y = wp[1];                               \
            if (bn + 2 < Nd) bv1.z = wp[2];                               \
            if (bn + 3 < Nd) bv1.w = wp[3];                               \
        }                                                                 \
    }

#define GEMM_STS(BUF)                                                     \
    {                                                                     \
        *(float4*)&As[BUF][arow][ak]   = av;                              \
        *(float4*)&Bs[BUF][bk][bn]     = bv0;                             \
        *(float4*)&Bs[BUF][bk + 8][bn] = bv1;                             \
    }

    const int nT = (Kd + 15) / 16;
    GEMM_LDG(0);
    GEMM_STS(0);
    __syncthreads();

    for (int t = 0; t < nT; t++) {
        const int cur = t & 1;
        if (t + 1 < nT) GEMM_LDG((t + 1) * 16);

#pragma unroll
        for (int kk4 = 0; kk4 < 16; kk4 += 4) {
            float4 b0 = *(const float4*)&Bs[cur][kk4 + 0][tn * 4];
            float4 b1 = *(const float4*)&Bs[cur][kk4 + 1][tn * 4];
            float4 b2 = *(const float4*)&Bs[cur][kk4 + 2][tn * 4];
            float4 b3 = *(const float4*)&Bs[cur][kk4 + 3][tn * 4];
#pragma unroll
            for (int i = 0; i < 8; i++) {
                float4 a = *(const float4*)&As[cur][tm * 8 + i][kk4];
                acc[i][0] = fmaf(a.x, b0.x, acc[i][0]);
                acc[i][1] = fmaf(a.x, b0.y, acc[i][1]);
                acc[i][2] = fmaf(a.x, b0.z, acc[i][2]);
                acc[i][3] = fmaf(a.x, b0.w, acc[i][3]);
                acc[i][0] = fmaf(a.y, b1.x, acc[i][0]);
                acc[i][1] = fmaf(a.y, b1.y, acc[i][1]);
                acc[i][2] = fmaf(a.y, b1.z, acc[i][2]);
                acc[i][3] = fmaf(a.y, b1.w, acc[i][3]);
                acc[i][0] = fmaf(a.z, b2.x, acc[i][0]);
                acc[i][1] = fmaf(a.z, b2.y, acc[i][1]);
                acc[i][2] = fmaf(a.z, b2.z, acc[i][2]);
                acc[i][3] = fmaf(a.z, b2.w, acc[i][3]);
                acc[i][0] = fmaf(a.w, b3.x, acc[i][0]);
                acc[i][1] = fmaf(a.w, b3.y, acc[i][1]);
                acc[i][2] = fmaf(a.w, b3.z, acc[i][2]);
                acc[i][3] = fmaf(a.w, b3.w, acc[i][3]);
            }
        }

        if (t + 1 < nT) GEMM_STS(cur ^ 1);
        __syncthreads();
    }

#pragma unroll
    for (int i = 0; i < 8; i++) {
        int row = m0 + tm * 8 + i;
#pragma unroll
        for (int j = 0; j < 4; j++) {
            int col = tn * 4 + j;
            if (col < Nd) {
                float v = acc[i][j] + bias[col];
                if (relu) v = fmaxf(v, 0.f);
                C[(long)row * ldc + col] = v;
            }
        }
    }
}

// ------- thin GEMM (Nd=4), thread per row: y = A[:, :128](stride lda) @ W + b -----
__global__ __launch_bounds__(256) void thin_kernel(
    const float* __restrict__ A, int lda,
    const float* __restrict__ Wg,     // [128, 4]
    const float* __restrict__ bg,
    float4* __restrict__ y, float* __restrict__ s2)
{
    __shared__ float4 Ws[128];
    const int tid = threadIdx.x;
    if (tid < 128) Ws[tid] = ((const float4*)Wg)[tid];
    __syncthreads();

    const int row = blockIdx.x * 256 + tid;
    const float4* xr = (const float4*)(A + (long)row * lda);
    float4 acc = make_float4(bg[0], bg[1], bg[2], bg[3]);
#pragma unroll
    for (int k4 = 0; k4 < 32; k4++) {
        float4 xv = xr[k4];
        float4 w0 = Ws[k4 * 4 + 0];
        float4 w1 = Ws[k4 * 4 + 1];
        float4 w2 = Ws[k4 * 4 + 2];
        float4 w3 = Ws[k4 * 4 + 3];
        acc.x = fmaf(xv.x, w0.x, acc.x); acc.y = fmaf(xv.x, w0.y, acc.y);
        acc.z = fmaf(xv.x, w0.z, acc.z); acc.w = fmaf(xv.x, w0.w, acc.w);
        acc.x = fmaf(xv.y, w1.x, acc.x); acc.y = fmaf(xv.y, w1.y, acc.y);
        acc.z = fmaf(xv.y, w1.z, acc.z); acc.w = fmaf(xv.y, w1.w, acc.w);
        acc.x = fmaf(xv.z, w2.x, acc.x); acc.y = fmaf(xv.z, w2.y, acc.y);
        acc.z = fmaf(xv.z, w2.z, acc.z); acc.w = fmaf(xv.z, w2.w, acc.w);
        acc.x = fmaf(xv.w, w3.x, acc.x); acc.y = fmaf(xv.w, w3.y, acc.y);
        acc.z = fmaf(xv.w, w3.z, acc.z); acc.w = fmaf(xv.w, w3.w, acc.w);
    }
    y[row] = acc;
    if (s2) s2[row] = acc.x * acc.x + acc.y * acc.y + acc.z * acc.z + acc.w * acc.w;
}

// ---------------- kNN: 4 queries/warp, 64-candidate groups, interleaved ranks ----
// Rank r in [0,64): lane = r>>1, slot = r&1. Shift-by-one insert = 1 shfl_up.
// Scan: each lane evaluates 2 candidates; one ballot on min(e_a,e_b) per group.
// e-space values: e = d2 - s2i (monotone in d2).
__global__ __launch_bounds__(WPB * 32) void knn_kernel(
    const float4* __restrict__ s, const float* __restrict__ s2,
    float* __restrict__ kd, int* __restrict__ kj)
{
    __shared__ float4 sj[TJ];
    __shared__ float  s2j[TJ];

    const unsigned F = 0xffffffffu;
    const int tid  = threadIdx.x;
    const int lane = tid & 31;
    const int warp = tid >> 5;
    const int qb   = (blockIdx.x * WPB + warp) * WQ;
    const int r0   = 2 * lane;
    const int r1   = 2 * lane + 1;

    float m2x[WQ], m2y[WQ], m2z[WQ], m2w[WQ], s2i[WQ];
    float q0v[WQ], q1v[WQ], thrE[WQ];
    int   q0j[WQ], q1j[WQ];

#pragma unroll
    for (int u = 0; u < WQ; u++) {
        float4 si = s[qb + u];
        s2i[u] = s2[qb + u];
        m2x[u] = -2.f * si.x; m2y[u] = -2.f * si.y;
        m2z[u] = -2.f * si.z; m2w[u] = -2.f * si.w;
        q0v[u] = FLT_MAX; q1v[u] = FLT_MAX;
        q0j[u] = 0;       q1j[u] = 0;
        thrE[u] = FLT_MAX;
    }

#define KNN_INSERT(u, v, j)                                               \
    {                                                                     \
        unsigned b0 = __ballot_sync(F, q0v[u] < (v));                     \
        unsigned b1 = __ballot_sync(F, q1v[u] < (v));                     \
        const int p = __popc(b0) + __popc(b1);                            \
        float s1v = __shfl_up_sync(F, q1v[u], 1);                         \
        int   s1j = __shfl_up_sync(F, q1j[u], 1);                         \
        const float oq0v = q0v[u];                                        \
        const int   oq0j = q0j[u];                                        \
        if (r0 == p)      { q0v[u] = (v);  q0j[u] = (j);  }               \
        else if (r0 > p)  { q0v[u] = s1v;  q0j[u] = s1j;  }               \
        if (r1 == p)      { q1v[u] = (v);  q1j[u] = (j);  }               \
        else if (r1 > p)  { q1v[u] = oq0v; q1j[u] = oq0j; }               \
    }

    for (int t0 = 0; t0 < NQ; t0 += TJ) {
        __syncthreads();
        sj[tid]        = s[t0 + tid];
        sj[tid + 256]  = s[t0 + tid + 256];
        s2j[tid]       = s2[t0 + tid];
        s2j[tid + 256] = s2[t0 + tid + 256];
        __syncthreads();

        for (int g = 0; g < TJ / 64; g++) {
            const int ca = g * 64 + lane;
            const int jbase = t0 + g * 64;
            const float4 A4 = sj[ca];
            const float4 B4 = sj[ca + 32];
            const float  za = s2j[ca];
            const float  zb = s2j[ca + 32];
#pragma unroll
            for (int u = 0; u < WQ; u++) {
                float ea = fmaf(m2x[u], A4.x,
                           fmaf(m2y[u], A4.y,
                           fmaf(m2z[u], A4.z,
                           fmaf(m2w[u], A4.w, za))));
                float eb = fmaf(m2x[u], B4.x,
                           fmaf(m2y[u], B4.y,
                           fmaf(m2z[u], B4.z,
                           fmaf(m2w[u], B4.w, zb))));
                const float thr0 = thrE[u];
                unsigned m = __ballot_sync(F, fminf(ea, eb) < thr0);
                if (m) {
                    do {
                        const int src = __ffs(m) - 1; m &= m - 1;
                        const float va = __shfl_sync(F, ea, src);
                        const float vb = __shfl_sync(F, eb, src);
                        if (va < thr0) KNN_INSERT(u, va, jbase + src);
                        if (vb < thr0) KNN_INSERT(u, vb, jbase + 32 + src);
                    } while (m);
                    thrE[u] = __shfl_sync(F, q1v[u], 19);   // rank 39
                }
            }
        }
    }

#pragma unroll
    for (int u = 0; u < WQ; u++) {
        const int q = qb + u;
        if (lane < 20) {                       // ranks 0..39
            kd[q * KNN + r0] = q0v[u] + s2i[u];
            kj[q * KNN + r0] = q0j[u];
            kd[q * KNN + r1] = q1v[u] + s2i[u];
            kj[q * KNN + r1] = q1j[u];
        }
    }
}

// ---------------- aggregate: warp per query, mean||max of h[idx]*w ---------------
__global__ void aggregate_kernel(
    const float* __restrict__ h, const float* __restrict__ kd,
    const int* __restrict__ kj, float* __restrict__ xcat)
{
    int gw   = (blockIdx.x * blockDim.x + threadIdx.x) >> 5;  // query
    int lane = threadIdx.x & 31;

    const float* dd = kd + gw * KNN;
    const int*   jj = kj + gw * KNN;

    float m0 = 0.f, m1 = 0.f;
    float x0 = -FLT_MAX, x1 = -FLT_MAX;
#pragma unroll
    for (int k = 0; k < KNN; k++) {
        int   j = jj[k];
        float w = expf(-10.f * fmaxf(dd[k], 0.f));
        float v0 = h[j * PROP + lane] * w;
        float v1 = h[j * PROP + 32 + lane] * w;
        m0 += v0; m1 += v1;
        x0 = fmaxf(x0, v0); x1 = fmaxf(x1, v1);
    }
    float* out = xcat + (long)gw * 256 + 128;
    const float inv = 1.f / (float)KNN;
    out[lane]      = m0 * inv;
    out[32 + lane] = m1 * inv;
    out[64 + lane] = x0;
    out[96 + lane] = x1;
}

// =================================================================================
extern "C" void kernel_launch(void* const* d_in, const int* in_sizes, int n_in,
                              void* d_out, int out_size)
{
    const float* x    = (const float*)d_in[0];
    const float* fc1W = (const float*)d_in[1];
    const float* fc1b = (const float*)d_in[2];
    const float* fc2W = (const float*)d_in[3];
    const float* fc2b = (const float*)d_in[4];
    const float* gsW  = (const float*)d_in[5];
    const float* gsb  = (const float*)d_in[6];
    const float* ghW  = (const float*)d_in[7];
    const float* ghb  = (const float*)d_in[8];
    const float* goW  = (const float*)d_in[9];
    const float* gob  = (const float*)d_in[10];
    const float* d1W  = (const float*)d_in[11];
    const float* d1b  = (const float*)d_in[12];
    const float* d2W  = (const float*)d_in[13];
    const float* d2b  = (const float*)d_in[14];
    const float* d3W  = (const float*)d_in[15];
    const float* d3b  = (const float*)d_in[16];
    const float* fc3W = (const float*)d_in[17];
    const float* fc3b = (const float*)d_in[18];
    const float* fc4W = (const float*)d_in[19];
    const float* fc4b = (const float*)d_in[20];
    float* out = (float*)d_out;

    float *t1, *t2, *xcat, *xg, *s, *s2n, *h, *kd;
    int *kj;
    cudaGetSymbolAddress((void**)&t1,   g_t1);
    cudaGetSymbolAddress((void**)&t2,   g_t2);
    cudaGetSymbolAddress((void**)&xcat, g_xcat);
    cudaGetSymbolAddress((void**)&xg,   g_xg);
    cudaGetSymbolAddress((void**)&s,    g_s);
    cudaGetSymbolAddress((void**)&s2n,  g_s2);
    cudaGetSymbolAddress((void**)&h,    g_h);
    cudaGetSymbolAddress((void**)&kd,   g_kd);
    cudaGetSymbolAddress((void**)&kj,   g_kj);

    const int GB = NQ / 64;  // gemm grid

    gemm_kernel<<<GB, 256>>>(x, 9, fc1W, fc1b, t1, HID, 9, HID, 1);          // my #1
    gemm_kernel<<<GB, 256>>>(t1, HID, fc2W, fc2b, xcat, 256, HID, HID, 1);   // my #2

    for (int l = 0; l < 4; l++) {
        // thin -> knn first (knn depends only on thin); gh before aggregate.
        thin_kernel<<<NQ / 256, 256>>>(xcat, 256, gsW + l * HID * SPACE,
                                       gsb + l * SPACE, (float4*)s, s2n);    // my #3
        knn_kernel<<<NQ / (WPB * WQ), WPB * 32>>>((const float4*)s, s2n, kd, kj); // my #4 (global #6 -> ncu)
        gemm_kernel<<<GB, 256>>>(xcat, 256, ghW + l * HID * PROP, ghb + l * PROP,
                                 h, PROP, HID, PROP, 0);
        aggregate_kernel<<<NQ / 8, 256>>>(h, kd, kj, xcat);
        gemm_kernel<<<GB, 256>>>(xcat, 256, goW + l * 256 * HID, gob + l * HID,
                                 xg, HID, 256, HID, 0);
        gemm_kernel<<<GB, 256>>>(xg, HID, d1W + l * HID * HID, d1b + l * HID,
                                 t1, HID, HID, HID, 1);
        gemm_kernel<<<GB, 256>>>(t1, HID, d2W + l * HID * HID, d2b + l * HID,
                                 t2, HID, HID, HID, 1);
        gemm_kernel<<<GB, 256>>>(t2, HID, d3W + l * HID * HID, d3b + l * HID,
                                 xcat, 256, HID, HID, 1);
    }

    gemm_kernel<<<GB, 256>>>(xcat, 256, fc3W, fc3b, t1, HID, HID, HID, 1);
    thin_kernel<<<NQ / 256, 256>>>(t1, HID, fc4W, fc4b, (float4*)out, nullptr);
}